// round 8
// baseline (speedup 1.0000x reference)
#include <cuda_runtime.h>
#include <cuda_bf16.h>
#include <cstdint>
#include <cstddef>

// Problem constants
#define BATCH   4
#define SEQ     2048
#define DMODEL  512
#define NHEADS  8
#define HDIM    64
#define DFF     2048
#define NLAYERS 6
#define MROWS   (BATCH * SEQ)            // 8192

// -------- scratch (device globals; no allocation allowed) --------
__device__ float g_x   [MROWS * DMODEL];   // fp32 residual stream
__device__ float g_xr  [MROWS * DMODEL];   // tf32-rounded copy (gemm A input)
__device__ float g_q   [MROWS * DMODEL];
__device__ float g_k   [MROWS * DMODEL];
__device__ float g_v   [MROWS * DMODEL];
__device__ float g_attn[MROWS * DMODEL];
__device__ float g_tmp [MROWS * DMODEL];
__device__ float g_ff  [MROWS * DFF];
// tf32-rounded weights
#define WR_TOTAL 18874368
__device__ float g_wr  [WR_TOTAL];

// ==================== helpers ====================
__device__ __forceinline__ uint32_t f2tf32(float x) {
    uint32_t u;
    asm("cvt.rna.tf32.f32 %0, %1;" : "=r"(u) : "f"(x));
    return u;
}
__device__ __forceinline__ float rnd_tf32(float x) {
    return __uint_as_float(f2tf32(x));
}
__device__ __forceinline__ uint4 cvt4(float4 v) {
    return make_uint4(f2tf32(v.x), f2tf32(v.y), f2tf32(v.z), f2tf32(v.w));
}
__device__ __forceinline__ uint32_t smem_u32(const void* p) {
    uint32_t a;
    asm("{ .reg .u64 t; cvta.to.shared.u64 t, %1; cvt.u32.u64 %0, t; }"
        : "=r"(a) : "l"(p));
    return a;
}
__device__ __forceinline__ void cp16(uint32_t dst, const void* src) {
    asm volatile("cp.async.cg.shared.global [%0], [%1], 16;"
                 :: "r"(dst), "l"(src));
}
#define CP_COMMIT() asm volatile("cp.async.commit_group;" ::: "memory")
#define CP_WAIT0()  asm volatile("cp.async.wait_group 0;" ::: "memory")
#define CP_WAIT1()  asm volatile("cp.async.wait_group 1;" ::: "memory")

// mma.sync m16n8k8 tf32: d = a*b + c  (f32 accum)
__device__ __forceinline__ void mma_tf32(
    float* d, const uint32_t* a, const uint32_t* b, const float* c)
{
    asm volatile(
        "mma.sync.aligned.m16n8k8.row.col.f32.tf32.tf32.f32 "
        "{%0,%1,%2,%3}, {%4,%5,%6,%7}, {%8,%9}, {%10,%11,%12,%13};"
        : "=f"(d[0]), "=f"(d[1]), "=f"(d[2]), "=f"(d[3])
        : "r"(a[0]), "r"(a[1]), "r"(a[2]), "r"(a[3]),
          "r"(b[0]), "r"(b[1]),
          "f"(c[0]), "f"(c[1]), "f"(c[2]), "f"(c[3]));
}

// =====================================================================
// Weight rounding passes (z-indexed, 2 launches total)
// =====================================================================
__global__ void __launch_bounds__(256) round4_kernel(
    const float* __restrict__ s0, const float* __restrict__ s1,
    const float* __restrict__ s2, const float* __restrict__ s3,
    float* __restrict__ d0, float* __restrict__ d1,
    float* __restrict__ d2, float* __restrict__ d3)
{
    const float* s; float* d;
    if (blockIdx.z == 0)      { s = s0; d = d0; }
    else if (blockIdx.z == 1) { s = s1; d = d1; }
    else if (blockIdx.z == 2) { s = s2; d = d2; }
    else                      { s = s3; d = d3; }
    int i = blockIdx.x * blockDim.x + threadIdx.x;
    float4 v = *(const float4*)(s + (size_t)i * 4);
    *(uint4*)(d + (size_t)i * 4) = cvt4(v);
}

__global__ void __launch_bounds__(256) round2_kernel(
    const float* __restrict__ s0, const float* __restrict__ s1,
    float* __restrict__ d0, float* __restrict__ d1)
{
    const float* s; float* d;
    if (blockIdx.z == 0) { s = s0; d = d0; }
    else                 { s = s1; d = d1; }
    int i = blockIdx.x * blockDim.x + threadIdx.x;
    float4 v = *(const float4*)(s + (size_t)i * 4);
    *(uint4*)(d + (size_t)i * 4) = cvt4(v);
}

// =====================================================================
// Embedding + positional encoding: dual write (fp32 + rounded)
// =====================================================================
__global__ void __launch_bounds__(128) embed_kernel(
    const int* __restrict__ src, const float* __restrict__ emb,
    const float* __restrict__ pe, float* __restrict__ xf,
    float* __restrict__ xr)
{
    int bl  = blockIdx.x;
    int l   = bl & (SEQ - 1);
    int tok = src[bl];
    int c   = threadIdx.x * 4;
    float4 e = *(const float4*)(emb + (size_t)tok * DMODEL + c);
    float4 p = *(const float4*)(pe  + (size_t)l   * DMODEL + c);
    float4 o; o.x = e.x + p.x; o.y = e.y + p.y; o.z = e.z + p.z; o.w = e.w + p.w;
    *(float4*)(xf + (size_t)bl * DMODEL + c) = o;
    *(uint4*)(xr + (size_t)bl * DMODEL + c) = cvt4(o);
}

// =====================================================================
// Tensor-core GEMM v3 (tf32 mma.sync): C = A@W + bias (+res)(+relu)(+rnd)
// Both operands pre-rounded tf32 in gmem -> pure cp.async pipeline.
// CTA 128x128, 8 warps (2x4, warp tile 64x32), KC=32, 3-stage pipeline.
// =====================================================================
#define KC3    32
#define AW     36
#define BW     136
#define A_STG  (128 * AW)
#define B_STG  (KC3 * BW)
#define STG_W  (A_STG + B_STG)
#define GS3_SMEM (3 * STG_W * 4)          // 107520 bytes

__device__ __forceinline__ void gemm_body(
    const float* __restrict__ A, const float* __restrict__ Wr,
    const float* __restrict__ bias, const float* __restrict__ res,
    float* __restrict__ C, int M, int N, int K, int relu, int rnd,
    int bxx, int byy)
{
    extern __shared__ uint32_t sm[];
    uint32_t sbase = smem_u32(sm);

    int tid  = threadIdx.x;
    int lane = tid & 31;
    int wid  = tid >> 5;
    int bm = byy << 7, bn = bxx << 7;
    int warpM = (wid >> 2) * 64;
    int warpN = (wid & 3) * 32;
    int r0 = lane >> 2, c0 = lane & 3;

    int aRow[4], aC16[4], bKr[4], bC16[4];
#pragma unroll
    for (int i = 0; i < 4; i++) {
        int id = tid + i * 256;
        aRow[i] = id >> 3;  aC16[i] = id & 7;
        bKr[i]  = id >> 5;  bC16[i] = id & 31;
    }

    float acc[4][4][4];
#pragma unroll
    for (int mt = 0; mt < 4; mt++)
#pragma unroll
        for (int nt = 0; nt < 4; nt++)
#pragma unroll
            for (int r = 0; r < 4; r++) acc[mt][nt][r] = 0.f;

    int nst = K / KC3;

    auto issue_stage = [&](int st, int kc) {
        uint32_t aB = sbase + (st * STG_W) * 4;
        uint32_t bBq = sbase + (st * STG_W + A_STG) * 4;
#pragma unroll
        for (int i = 0; i < 4; i++)
            cp16(aB + (aRow[i] * AW + aC16[i] * 4) * 4,
                 A + (size_t)(bm + aRow[i]) * K + kc + aC16[i] * 4);
#pragma unroll
        for (int i = 0; i < 4; i++)
            cp16(bBq + (bKr[i] * BW + bC16[i] * 4) * 4,
                 Wr + (size_t)(kc + bKr[i]) * N + bn + bC16[i] * 4);
        CP_COMMIT();
    };

    issue_stage(0, 0);
    issue_stage(1, KC3);

    for (int s = 0; s < nst; s++) {
        int cur = s % 3;
        if (s + 1 < nst) CP_WAIT1(); else CP_WAIT0();
        __syncthreads();
        if (s + 2 < nst) issue_stage((s + 2) % 3, (s + 2) * KC3);

        const uint32_t* Ab = sm + cur * STG_W;
        const uint32_t* Bb = Ab + A_STG;
#pragma unroll
        for (int ks = 0; ks < 4; ks++) {
            int k0 = ks * 8 + c0;
            uint32_t af[4][4], bf[4][2];
#pragma unroll
            for (int mt = 0; mt < 4; mt++) {
                int m0 = warpM + mt * 16 + r0;
                af[mt][0] = Ab[m0 * AW + k0];
                af[mt][1] = Ab[(m0 + 8) * AW + k0];
                af[mt][2] = Ab[m0 * AW + k0 + 4];
                af[mt][3] = Ab[(m0 + 8) * AW + k0 + 4];
            }
#pragma unroll
            for (int nt = 0; nt < 4; nt++) {
                int n0 = warpN + nt * 8 + r0;
                bf[nt][0] = Bb[k0 * BW + n0];
                bf[nt][1] = Bb[(k0 + 4) * BW + n0];
            }
#pragma unroll
            for (int mt = 0; mt < 4; mt++)
#pragma unroll
                for (int nt = 0; nt < 4; nt++)
                    mma_tf32(acc[mt][nt], af[mt], bf[nt], acc[mt][nt]);
        }
        __syncthreads();
    }

#pragma unroll
    for (int mt = 0; mt < 4; mt++) {
        int row0 = bm + warpM + mt * 16 + r0;
#pragma unroll
        for (int h = 0; h < 2; h++) {
            int row = row0 + h * 8;
            float* crow = C + (size_t)row * N;
            const float* rrow = res ? (res + (size_t)row * N) : nullptr;
#pragma unroll
            for (int nt = 0; nt < 4; nt++) {
                int col = bn + warpN + nt * 8 + 2 * c0;
                float2 b2 = *(const float2*)(bias + col);
                float2 o;
                o.x = acc[mt][nt][h * 2 + 0] + b2.x;
                o.y = acc[mt][nt][h * 2 + 1] + b2.y;
                if (rrow) {
                    float2 r2 = *(const float2*)(rrow + col);
                    o.x += r2.x; o.y += r2.y;
                }
                if (relu) { o.x = fmaxf(o.x, 0.f); o.y = fmaxf(o.y, 0.f); }
                if (rnd)  { o.x = rnd_tf32(o.x);   o.y = rnd_tf32(o.y); }
                *(float2*)(crow + col) = o;
            }
        }
    }
}

__global__ void __launch_bounds__(256, 2) gemm_mma(
    const float* __restrict__ A, const float* __restrict__ Wr,
    const float* __restrict__ bias, const float* __restrict__ res,
    float* __restrict__ C, int M, int N, int K, int relu, int rnd)
{
    gemm_body(A, Wr, bias, res, C, M, N, K, relu, rnd,
              blockIdx.x, blockIdx.y);
}

__global__ void __launch_bounds__(256, 2) gemm_qkv(
    const float* __restrict__ x,
    const float* __restrict__ Wq, const float* __restrict__ Wk,
    const float* __restrict__ Wv,
    const float* __restrict__ bq, const float* __restrict__ bk,
    const float* __restrict__ bv,
    float* __restrict__ q, float* __restrict__ k, float* __restrict__ v)
{
    const float* W; const float* bias; float* C;
    if (blockIdx.z == 0)      { W = Wq; bias = bq; C = q; }
    else if (blockIdx.z == 1) { W = Wk; bias = bk; C = k; }
    else                      { W = Wv; bias = bv; C = v; }
    gemm_body(x, W, bias, nullptr, C, MROWS, DMODEL, DMODEL, 0, 1,
              blockIdx.x, blockIdx.y);
}

// =====================================================================
// Tensor-core flash attention (tf32 mma.sync), cp.async, dbuf K/V.
// V stored with stride 72 (conflict-free fragment loads); K/Q/P stride 68.
// smem layout (words): Q[0] P[4352] K0[8704] K1[13056] V0[17408] V1[22016]
// =====================================================================
#define ATS 68
#define VTS 72
#define TILE_W  (64 * ATS)                // 4352
#define VTILE_W (64 * VTS)                // 4608
#define ATTN3_SMEM ((4 * TILE_W + 2 * VTILE_W) * 4)   // 106496 bytes

__device__ __forceinline__ void cp_tile(
    uint32_t dstbase, const float* __restrict__ g, int tid, int stride)
{
#pragma unroll
    for (int i = 0; i < 8; i++) {
        int id  = tid + i * 128;
        int row = id >> 4, c16 = id & 15;
        cp16(dstbase + (row * stride + c16 * 4) * 4, g + row * 64 + c16 * 4);
    }
}

__global__ void __launch_bounds__(128, 2) attn_mma(
    const float* __restrict__ q, const float* __restrict__ k,
    const float* __restrict__ v, float* __restrict__ out)
{
    extern __shared__ uint32_t smu[];
    uint32_t sbase = smem_u32(smu);
    uint32_t* Qs = smu;
    uint32_t* Ps = smu + TILE_W;

    int tid  = threadIdx.x;
    int lane = tid & 31;
    int wid  = tid >> 5;
    int bh   = blockIdx.y;
    int qt   = blockIdx.x;
    int b    = bh >> 3, h = bh & 7;

    const float* Qg = q + ((size_t)bh * SEQ + qt * 64) * HDIM;
    const float* Kg = k + (size_t)bh * SEQ * HDIM;
    const float* Vg = v + (size_t)bh * SEQ * HDIM;

    cp_tile(sbase, Qg, tid, ATS);
    cp_tile(sbase + (2 * TILE_W) * 4, Kg, tid, ATS);
    cp_tile(sbase + (4 * TILE_W) * 4, Vg, tid, VTS);
    CP_COMMIT();

    int warpM = wid * 16;
    int r0 = lane >> 2, c0 = lane & 3;

    float m0 = -1e30f, m1 = -1e30f, l0 = 0.f, l1 = 0.f;
    float o_acc[8][4];
#pragma unroll
    for (int nt = 0; nt < 8; nt++)
#pragma unroll
        for (int r = 0; r < 4; r++) o_acc[nt][r] = 0.f;

    for (int kt = 0; kt < SEQ / 64; kt++) {
        int cur = kt & 1, nb = cur ^ 1;
        CP_WAIT0();
        __syncthreads();
        if (kt + 1 < SEQ / 64) {
            cp_tile(sbase + ((2 + nb) * TILE_W) * 4,
                    Kg + (size_t)(kt + 1) * 64 * HDIM, tid, ATS);
            cp_tile(sbase + (4 * TILE_W + nb * VTILE_W) * 4,
                    Vg + (size_t)(kt + 1) * 64 * HDIM, tid, VTS);
            CP_COMMIT();
        }
        const uint32_t* Ks = smu + (2 + cur) * TILE_W;
        const uint32_t* Vs = smu + 4 * TILE_W + cur * VTILE_W;

        // ---- S = Q K^T ----
        float sacc[8][4];
#pragma unroll
        for (int nt = 0; nt < 8; nt++)
#pragma unroll
            for (int r = 0; r < 4; r++) sacc[nt][r] = 0.f;

#pragma unroll
        for (int ks = 0; ks < 8; ks++) {
            int kk = ks * 8 + c0;
            uint32_t a[4];
            a[0] = Qs[(warpM + r0) * ATS + kk];
            a[1] = Qs[(warpM + r0 + 8) * ATS + kk];
            a[2] = Qs[(warpM + r0) * ATS + kk + 4];
            a[3] = Qs[(warpM + r0 + 8) * ATS + kk + 4];
#pragma unroll
            for (int nt = 0; nt < 8; nt++) {
                uint32_t bb[2];
                bb[0] = Ks[(nt * 8 + r0) * ATS + kk];
                bb[1] = Ks[(nt * 8 + r0) * ATS + kk + 4];
                mma_tf32(sacc[nt], a, bb, sacc[nt]);
            }
        }

        // ---- online softmax ----
        float mt0 = -1e30f, mt1 = -1e30f;
#pragma unroll
        for (int nt = 0; nt < 8; nt++) {
#pragma unroll
            for (int r = 0; r < 4; r++) sacc[nt][r] *= 0.125f;
            mt0 = fmaxf(mt0, fmaxf(sacc[nt][0], sacc[nt][1]));
            mt1 = fmaxf(mt1, fmaxf(sacc[nt][2], sacc[nt][3]));
        }
        mt0 = fmaxf(mt0, __shfl_xor_sync(0xffffffffu, mt0, 1));
        mt0 = fmaxf(mt0, __shfl_xor_sync(0xffffffffu, mt0, 2));
        mt1 = fmaxf(mt1, __shfl_xor_sync(0xffffffffu, mt1, 1));
        mt1 = fmaxf(mt1, __shfl_xor_sync(0xffffffffu, mt1, 2));

        float mn0 = fmaxf(m0, mt0), mn1 = fmaxf(m1, mt1);
        float corr0 = __expf(m0 - mn0), corr1 = __expf(m1 - mn1);
        m0 = mn0; m1 = mn1;

        float rs0 = 0.f, rs1 = 0.f;
#pragma unroll
        for (int nt = 0; nt < 8; nt++) {
            float p00 = __expf(sacc[nt][0] - mn0);
            float p01 = __expf(sacc[nt][1] - mn0);
            float p10 = __expf(sacc[nt][2] - mn1);
            float p11 = __expf(sacc[nt][3] - mn1);
            rs0 += p00 + p01; rs1 += p10 + p11;
            uint2 u0 = make_uint2(f2tf32(p00), f2tf32(p01));
            uint2 u1 = make_uint2(f2tf32(p10), f2tf32(p11));
            *(uint2*)&Ps[(warpM + r0) * ATS + nt * 8 + 2 * c0] = u0;
            *(uint2*)&Ps[(warpM + r0 + 8) * ATS + nt * 8 + 2 * c0] = u1;
        }
        rs0 += __shfl_xor_sync(0xffffffffu, rs0, 1);
        rs0 += __shfl_xor_sync(0xffffffffu, rs0, 2);
        rs1 += __shfl_xor_sync(0xffffffffu, rs1, 1);
        rs1 += __shfl_xor_sync(0xffffffffu, rs1, 2);
        l0 = l0 * corr0 + rs0;
        l1 = l1 * corr1 + rs1;

#pragma unroll
        for (int nt = 0; nt < 8; nt++) {
            o_acc[nt][0] *= corr0; o_acc[nt][1] *= corr0;
            o_acc[nt][2] *= corr1; o_acc[nt][3] *= corr1;
        }
        __syncwarp();

        // ---- O += P @ V ----
#pragma unroll
        for (int ks = 0; ks < 8; ks++) {
            int kk = ks * 8;
            uint32_t a[4];
            a[0] = Ps[(warpM + r0) * ATS + kk + c0];
            a[1] = Ps[(warpM + r0 + 8) * ATS + kk + c0];
            a[2] = Ps[(warpM + r0) * ATS + kk + c0 + 4];
            a[3] = Ps[(warpM + r0 + 8) * ATS + kk + c0 + 4];
#pragma unroll
            for (int nt = 0; nt < 8; nt++) {
                uint32_t bb[2];
                bb[0] = Vs[(kk + c0) * VTS + nt * 8 + r0];
                bb[1] = Vs[(kk + c0 + 4) * VTS + nt * 8 + r0];
                mma_tf32(o_acc[nt], a, bb, o_acc[nt]);
            }
        }
    }

    float inv0 = 1.0f / l0, inv1 = 1.0f / l1;
    size_t row0 = (size_t)b * SEQ + qt * 64 + warpM + r0;
    float* O0 = out + row0 * DMODEL + h * HDIM;
    float* O1 = O0 + 8 * DMODEL;
#pragma unroll
    for (int nt = 0; nt < 8; nt++) {
        int col = nt * 8 + 2 * c0;
        float2 a = make_float2(rnd_tf32(o_acc[nt][0] * inv0),
                               rnd_tf32(o_acc[nt][1] * inv0));
        float2 c = make_float2(rnd_tf32(o_acc[nt][2] * inv1),
                               rnd_tf32(o_acc[nt][3] * inv1));
        *(float2*)(O0 + col) = a;
        *(float2*)(O1 + col) = c;
    }
}

// =====================================================================
// LayerNorm over last dim (512). Block per row, 128 threads.
// Dual write: out_f = fp32 (residual stream), out_r = tf32-rounded
// (gemm A input). out_r may be null (final layer).
// =====================================================================
__global__ void __launch_bounds__(128) ln_kernel(
    const float* __restrict__ in, const float* __restrict__ g,
    const float* __restrict__ b, float* __restrict__ out_f,
    float* __restrict__ out_r)
{
    int row = blockIdx.x;
    int tid = threadIdx.x;
    float4 v4 = *(const float4*)(in + (size_t)row * DMODEL + tid * 4);
    float s  = v4.x + v4.y + v4.z + v4.w;
    float sq = v4.x * v4.x + v4.y * v4.y + v4.z * v4.z + v4.w * v4.w;
#pragma unroll
    for (int off = 16; off > 0; off >>= 1) {
        s  += __shfl_xor_sync(0xffffffffu, s, off);
        sq += __shfl_xor_sync(0xffffffffu, sq, off);
    }
    __shared__ float ss[4], sqs[4];
    int wid = tid >> 5;
    if ((tid & 31) == 0) { ss[wid] = s; sqs[wid] = sq; }
    __syncthreads();
    s  = ss[0] + ss[1] + ss[2] + ss[3];
    sq = sqs[0] + sqs[1] + sqs[2] + sqs[3];
    float mu  = s * (1.0f / DMODEL);
    float var = sq * (1.0f / DMODEL) - mu * mu;
    float inv = rsqrtf(var + 1e-5f);
    float4 gv = *(const float4*)(g + tid * 4);
    float4 bv = *(const float4*)(b + tid * 4);
    float4 o;
    o.x = (v4.x - mu) * inv * gv.x + bv.x;
    o.y = (v4.y - mu) * inv * gv.y + bv.y;
    o.z = (v4.z - mu) * inv * gv.z + bv.z;
    o.w = (v4.w - mu) * inv * gv.w + bv.w;
    *(float4*)(out_f + (size_t)row * DMODEL + tid * 4) = o;
    if (out_r)
        *(uint4*)(out_r + (size_t)row * DMODEL + tid * 4) = cvt4(o);
}

// =====================================================================
// host launcher
// =====================================================================
extern "C" void kernel_launch(void* const* d_in, const int* in_sizes, int n_in,
                              void* d_out, int out_size)
{
    const int*   src  = (const int*)  d_in[0];
    const float* emb  = (const float*)d_in[1];
    const float* pe   = (const float*)d_in[2];
    const float* Wq   = (const float*)d_in[3];
    const float* bq   = (const float*)d_in[4];
    const float* Wk   = (const float*)d_in[5];
    const float* bk   = (const float*)d_in[6];
    const float* Wv   = (const float*)d_in[7];
    const float* bv   = (const float*)d_in[8];
    const float* Wo   = (const float*)d_in[9];
    const float* bo   = (const float*)d_in[10];
    const float* W1   = (const float*)d_in[11];
    const float* b1   = (const float*)d_in[12];
    const float* W2   = (const float*)d_in[13];
    const float* b2   = (const float*)d_in[14];
    const float* g1   = (const float*)d_in[15];
    const float* be1  = (const float*)d_in[16];
    const float* g2   = (const float*)d_in[17];
    const float* be2  = (const float*)d_in[18];
    float* outp = (float*)d_out;

    float *x, *xr, *q, *k, *v, *attn, *tmp, *ff, *wr;
    cudaGetSymbolAddress((void**)&x,    g_x);
    cudaGetSymbolAddress((void**)&xr,   g_xr);
    cudaGetSymbolAddress((void**)&q,    g_q);
    cudaGetSymbolAddress((void**)&k,    g_k);
    cudaGetSymbolAddress((void**)&v,    g_v);
    cudaGetSymbolAddress((void**)&attn, g_attn);
    cudaGetSymbolAddress((void**)&tmp,  g_tmp);
    cudaGetSymbolAddress((void**)&ff,   g_ff);
    cudaGetSymbolAddress((void**)&wr,   g_wr);

    cudaFuncSetAttribute(attn_mma,
                         cudaFuncAttributeMaxDynamicSharedMemorySize, ATTN3_SMEM);
    cudaFuncSetAttribute(gemm_mma,
                         cudaFuncAttributeMaxDynamicSharedMemorySize, GS3_SMEM);
    cudaFuncSetAttribute(gemm_qkv,
                         cudaFuncAttributeMaxDynamicSharedMemorySize, GS3_SMEM);

    const size_t DD6 = (size_t)NLAYERS * DMODEL * DMODEL;
    const size_t DF6 = (size_t)NLAYERS * DMODEL * DFF;
    float* WqR = wr;
    float* WkR = WqR + DD6;
    float* WvR = WkR + DD6;
    float* WoR = WvR + DD6;
    float* W1R = WoR + DD6;
    float* W2R = W1R + DF6;

    // 2 round launches (also puts the first gemm_mma at ncu's -s 5 slot)
    round4_kernel<<<dim3((unsigned)(DD6 / 4 / 256), 1, 4), 256>>>(
        Wq, Wk, Wv, Wo, WqR, WkR, WvR, WoR);
    round2_kernel<<<dim3((unsigned)(DF6 / 4 / 256), 1, 2), 256>>>(
        W1, W2, W1R, W2R);

    embed_kernel<<<MROWS, 128>>>(src, emb, pe, x, xr);

    dim3 gQKV(DMODEL / 128, MROWS / 128, 3);
    dim3 gProj(DMODEL / 128, MROWS / 128);
    dim3 gFF1(DFF / 128,    MROWS / 128);
    dim3 gAttn(SEQ / 64, BATCH * NHEADS);

    for (int L = 0; L < NLAYERS; L++) {
        const size_t wdd = (size_t)L * DMODEL * DMODEL;
        const size_t wdf = (size_t)L * DMODEL * DFF;
        const size_t vd  = (size_t)L * DMODEL;
        const size_t vf  = (size_t)L * DFF;

        gemm_qkv<<<gQKV, 256, GS3_SMEM>>>(xr, WqR + wdd, WkR + wdd, WvR + wdd,
                                          bq + vd, bk + vd, bv + vd, q, k, v);

        attn_mma<<<gAttn, 128, ATTN3_SMEM>>>(q, k, v, attn);

        // launch #6 overall on L==0 -> ncu captures this gemm
        gemm_mma<<<gProj, 256, GS3_SMEM>>>(attn, WoR + wdd, bo + vd, x, tmp,
                                           MROWS, DMODEL, DMODEL, 0, 0);
        ln_kernel<<<MROWS, 128>>>(tmp, g1 + vd, be1 + vd, x, xr);

        gemm_mma<<<gFF1, 256, GS3_SMEM>>>(xr, W1R + wdf, b1 + vf, nullptr, ff,
                                          MROWS, DFF, DMODEL, 1, 1);
        gemm_mma<<<gProj, 256, GS3_SMEM>>>(ff, W2R + wdf, b2 + vd, x, tmp,
                                           MROWS, DMODEL, DFF, 0, 0);
        ln_kernel<<<MROWS, 128>>>(tmp, g2 + vd, be2 + vd,
                                  (L == NLAYERS - 1) ? outp : x,
                                  (L == NLAYERS - 1) ? nullptr : xr);
    }
}

// round 9
// speedup vs baseline: 1.4335x; 1.4335x over previous
#include <cuda_runtime.h>
#include <cuda_bf16.h>
#include <cstdint>
#include <cstddef>

// Problem constants
#define BATCH   4
#define SEQ     2048
#define DMODEL  512
#define NHEADS  8
#define HDIM    64
#define DFF     2048
#define NLAYERS 6
#define MROWS   (BATCH * SEQ)            // 8192

// -------- scratch (device globals; no allocation allowed) --------
__device__ float g_x   [MROWS * DMODEL];   // fp32 residual stream
__device__ float g_xr  [MROWS * DMODEL];   // tf32-rounded copy (gemm A input)
__device__ float g_q   [MROWS * DMODEL];
__device__ float g_k   [MROWS * DMODEL];
__device__ float g_v   [MROWS * DMODEL];
__device__ float g_attn[MROWS * DMODEL];
__device__ float g_tmp [MROWS * DMODEL];
__device__ float g_ff  [MROWS * DFF];
// tf32-rounded weights
#define WR_TOTAL 18874368
__device__ float g_wr  [WR_TOTAL];

// ==================== helpers ====================
__device__ __forceinline__ uint32_t f2tf32(float x) {
    uint32_t u;
    asm("cvt.rna.tf32.f32 %0, %1;" : "=r"(u) : "f"(x));
    return u;
}
__device__ __forceinline__ float rnd_tf32(float x) {
    return __uint_as_float(f2tf32(x));
}
__device__ __forceinline__ uint4 cvt4(float4 v) {
    return make_uint4(f2tf32(v.x), f2tf32(v.y), f2tf32(v.z), f2tf32(v.w));
}
__device__ __forceinline__ uint32_t smem_u32(const void* p) {
    uint32_t a;
    asm("{ .reg .u64 t; cvta.to.shared.u64 t, %1; cvt.u32.u64 %0, t; }"
        : "=r"(a) : "l"(p));
    return a;
}
__device__ __forceinline__ void cp16(uint32_t dst, const void* src) {
    asm volatile("cp.async.cg.shared.global [%0], [%1], 16;"
                 :: "r"(dst), "l"(src));
}
#define CP_COMMIT() asm volatile("cp.async.commit_group;" ::: "memory")
#define CP_WAIT0()  asm volatile("cp.async.wait_group 0;" ::: "memory")
#define CP_WAIT1()  asm volatile("cp.async.wait_group 1;" ::: "memory")

// mma.sync m16n8k8 tf32: d = a*b + c  (f32 accum)
__device__ __forceinline__ void mma_tf32(
    float* d, const uint32_t* a, const uint32_t* b, const float* c)
{
    asm volatile(
        "mma.sync.aligned.m16n8k8.row.col.f32.tf32.tf32.f32 "
        "{%0,%1,%2,%3}, {%4,%5,%6,%7}, {%8,%9}, {%10,%11,%12,%13};"
        : "=f"(d[0]), "=f"(d[1]), "=f"(d[2]), "=f"(d[3])
        : "r"(a[0]), "r"(a[1]), "r"(a[2]), "r"(a[3]),
          "r"(b[0]), "r"(b[1]),
          "f"(c[0]), "f"(c[1]), "f"(c[2]), "f"(c[3]));
}

// =====================================================================
// Weight rounding passes (z-indexed, 2 launches total)
// =====================================================================
__global__ void __launch_bounds__(256) round4_kernel(
    const float* __restrict__ s0, const float* __restrict__ s1,
    const float* __restrict__ s2, const float* __restrict__ s3,
    float* __restrict__ d0, float* __restrict__ d1,
    float* __restrict__ d2, float* __restrict__ d3)
{
    const float* s; float* d;
    if (blockIdx.z == 0)      { s = s0; d = d0; }
    else if (blockIdx.z == 1) { s = s1; d = d1; }
    else if (blockIdx.z == 2) { s = s2; d = d2; }
    else                      { s = s3; d = d3; }
    int i = blockIdx.x * blockDim.x + threadIdx.x;
    float4 v = *(const float4*)(s + (size_t)i * 4);
    *(uint4*)(d + (size_t)i * 4) = cvt4(v);
}

__global__ void __launch_bounds__(256) round2_kernel(
    const float* __restrict__ s0, const float* __restrict__ s1,
    float* __restrict__ d0, float* __restrict__ d1)
{
    const float* s; float* d;
    if (blockIdx.z == 0) { s = s0; d = d0; }
    else                 { s = s1; d = d1; }
    int i = blockIdx.x * blockDim.x + threadIdx.x;
    float4 v = *(const float4*)(s + (size_t)i * 4);
    *(uint4*)(d + (size_t)i * 4) = cvt4(v);
}

// =====================================================================
// Embedding + positional encoding: dual write (fp32 + rounded)
// =====================================================================
__global__ void __launch_bounds__(128) embed_kernel(
    const int* __restrict__ src, const float* __restrict__ emb,
    const float* __restrict__ pe, float* __restrict__ xf,
    float* __restrict__ xr)
{
    int bl  = blockIdx.x;
    int l   = bl & (SEQ - 1);
    int tok = src[bl];
    int c   = threadIdx.x * 4;
    float4 e = *(const float4*)(emb + (size_t)tok * DMODEL + c);
    float4 p = *(const float4*)(pe  + (size_t)l   * DMODEL + c);
    float4 o; o.x = e.x + p.x; o.y = e.y + p.y; o.z = e.z + p.z; o.w = e.w + p.w;
    *(float4*)(xf + (size_t)bl * DMODEL + c) = o;
    *(uint4*)(xr + (size_t)bl * DMODEL + c) = cvt4(o);
}

// =====================================================================
// Tensor-core GEMM v3 (tf32 mma.sync): C = A@W + bias (+res)(+relu)(+rnd)
// Both operands pre-rounded tf32 in gmem -> pure cp.async pipeline.
// CTA 128x128, 8 warps (2x4, warp tile 64x32), KC=32, 3-stage pipeline.
// =====================================================================
#define KC3    32
#define AW     36
#define BW     136
#define A_STG  (128 * AW)
#define B_STG  (KC3 * BW)
#define STG_W  (A_STG + B_STG)
#define GS3_SMEM (3 * STG_W * 4)          // 107520 bytes

__device__ __forceinline__ void gemm_body(
    const float* __restrict__ A, const float* __restrict__ Wr,
    const float* __restrict__ bias, const float* __restrict__ res,
    float* __restrict__ C, int M, int N, int K, int relu, int rnd,
    int bxx, int byy)
{
    extern __shared__ uint32_t sm[];
    uint32_t sbase = smem_u32(sm);

    int tid  = threadIdx.x;
    int lane = tid & 31;
    int wid  = tid >> 5;
    int bm = byy << 7, bn = bxx << 7;
    int warpM = (wid >> 2) * 64;
    int warpN = (wid & 3) * 32;
    int r0 = lane >> 2, c0 = lane & 3;

    int aRow[4], aC16[4], bKr[4], bC16[4];
#pragma unroll
    for (int i = 0; i < 4; i++) {
        int id = tid + i * 256;
        aRow[i] = id >> 3;  aC16[i] = id & 7;
        bKr[i]  = id >> 5;  bC16[i] = id & 31;
    }

    float acc[4][4][4];
#pragma unroll
    for (int mt = 0; mt < 4; mt++)
#pragma unroll
        for (int nt = 0; nt < 4; nt++)
#pragma unroll
            for (int r = 0; r < 4; r++) acc[mt][nt][r] = 0.f;

    int nst = K / KC3;

    auto issue_stage = [&](int st, int kc) {
        uint32_t aB = sbase + (st * STG_W) * 4;
        uint32_t bBq = sbase + (st * STG_W + A_STG) * 4;
#pragma unroll
        for (int i = 0; i < 4; i++)
            cp16(aB + (aRow[i] * AW + aC16[i] * 4) * 4,
                 A + (size_t)(bm + aRow[i]) * K + kc + aC16[i] * 4);
#pragma unroll
        for (int i = 0; i < 4; i++)
            cp16(bBq + (bKr[i] * BW + bC16[i] * 4) * 4,
                 Wr + (size_t)(kc + bKr[i]) * N + bn + bC16[i] * 4);
        CP_COMMIT();
    };

    issue_stage(0, 0);
    issue_stage(1, KC3);

    for (int s = 0; s < nst; s++) {
        int cur = s % 3;
        if (s + 1 < nst) CP_WAIT1(); else CP_WAIT0();
        __syncthreads();
        if (s + 2 < nst) issue_stage((s + 2) % 3, (s + 2) * KC3);

        const uint32_t* Ab = sm + cur * STG_W;
        const uint32_t* Bb = Ab + A_STG;
#pragma unroll
        for (int ks = 0; ks < 4; ks++) {
            int k0 = ks * 8 + c0;
            uint32_t af[4][4], bf[4][2];
#pragma unroll
            for (int mt = 0; mt < 4; mt++) {
                int m0 = warpM + mt * 16 + r0;
                af[mt][0] = Ab[m0 * AW + k0];
                af[mt][1] = Ab[(m0 + 8) * AW + k0];
                af[mt][2] = Ab[m0 * AW + k0 + 4];
                af[mt][3] = Ab[(m0 + 8) * AW + k0 + 4];
            }
#pragma unroll
            for (int nt = 0; nt < 4; nt++) {
                int n0 = warpN + nt * 8 + r0;
                bf[nt][0] = Bb[k0 * BW + n0];
                bf[nt][1] = Bb[(k0 + 4) * BW + n0];
            }
#pragma unroll
            for (int mt = 0; mt < 4; mt++)
#pragma unroll
                for (int nt = 0; nt < 4; nt++)
                    mma_tf32(acc[mt][nt], af[mt], bf[nt], acc[mt][nt]);
        }
        __syncthreads();
    }

#pragma unroll
    for (int mt = 0; mt < 4; mt++) {
        int row0 = bm + warpM + mt * 16 + r0;
#pragma unroll
        for (int h = 0; h < 2; h++) {
            int row = row0 + h * 8;
            float* crow = C + (size_t)row * N;
            const float* rrow = res ? (res + (size_t)row * N) : nullptr;
#pragma unroll
            for (int nt = 0; nt < 4; nt++) {
                int col = bn + warpN + nt * 8 + 2 * c0;
                float2 b2 = *(const float2*)(bias + col);
                float2 o;
                o.x = acc[mt][nt][h * 2 + 0] + b2.x;
                o.y = acc[mt][nt][h * 2 + 1] + b2.y;
                if (rrow) {
                    float2 r2 = *(const float2*)(rrow + col);
                    o.x += r2.x; o.y += r2.y;
                }
                if (relu) { o.x = fmaxf(o.x, 0.f); o.y = fmaxf(o.y, 0.f); }
                if (rnd)  { o.x = rnd_tf32(o.x);   o.y = rnd_tf32(o.y); }
                *(float2*)(crow + col) = o;
            }
        }
    }
}

__global__ void __launch_bounds__(256, 2) gemm_mma(
    const float* __restrict__ A, const float* __restrict__ Wr,
    const float* __restrict__ bias, const float* __restrict__ res,
    float* __restrict__ C, int M, int N, int K, int relu, int rnd)
{
    gemm_body(A, Wr, bias, res, C, M, N, K, relu, rnd,
              blockIdx.x, blockIdx.y);
}

__global__ void __launch_bounds__(256, 2) gemm_qkv(
    const float* __restrict__ x,
    const float* __restrict__ Wq, const float* __restrict__ Wk,
    const float* __restrict__ Wv,
    const float* __restrict__ bq, const float* __restrict__ bk,
    const float* __restrict__ bv,
    float* __restrict__ q, float* __restrict__ k, float* __restrict__ v)
{
    const float* W; const float* bias; float* C;
    if (blockIdx.z == 0)      { W = Wq; bias = bq; C = q; }
    else if (blockIdx.z == 1) { W = Wk; bias = bk; C = k; }
    else                      { W = Wv; bias = bv; C = v; }
    gemm_body(x, W, bias, nullptr, C, MROWS, DMODEL, DMODEL, 0, 1,
              blockIdx.x, blockIdx.y);
}

// =====================================================================
// Tensor-core flash attention (tf32 mma.sync), cp.async loads,
// double-buffered K/V — round-7 exact layout (uniform stride 68).
// smem: Q | P | K0 | V0 | K1 | V1, each 64x68 words.
// =====================================================================
#define ATS 68
#define TILE_W (64 * ATS)                 // 4352 words
#define ATTN3_SMEM (6 * TILE_W * 4)       // 104448 bytes

__device__ __forceinline__ void cp_tile(
    uint32_t dstbase, const float* __restrict__ g, int tid)
{
#pragma unroll
    for (int i = 0; i < 8; i++) {
        int id  = tid + i * 128;
        int row = id >> 4, c16 = id & 15;
        cp16(dstbase + (row * ATS + c16 * 4) * 4, g + row * 64 + c16 * 4);
    }
}

__global__ void __launch_bounds__(128, 2) attn_mma(
    const float* __restrict__ q, const float* __restrict__ k,
    const float* __restrict__ v, float* __restrict__ out)
{
    extern __shared__ uint32_t smu[];
    uint32_t sbase = smem_u32(smu);
    uint32_t* Qs = smu;
    uint32_t* Ps = smu + TILE_W;

    int tid  = threadIdx.x;
    int lane = tid & 31;
    int wid  = tid >> 5;
    int bh   = blockIdx.y;
    int qt   = blockIdx.x;
    int b    = bh >> 3, h = bh & 7;

    const float* Qg = q + ((size_t)bh * SEQ + qt * 64) * HDIM;
    const float* Kg = k + (size_t)bh * SEQ * HDIM;
    const float* Vg = v + (size_t)bh * SEQ * HDIM;

    // prolog: Q + K0 + V0 in one group
    cp_tile(sbase, Qg, tid);
    cp_tile(sbase + (2 * TILE_W) * 4, Kg, tid);
    cp_tile(sbase + (3 * TILE_W) * 4, Vg, tid);
    CP_COMMIT();

    int warpM = wid * 16;
    int r0 = lane >> 2, c0 = lane & 3;

    float m0 = -1e30f, m1 = -1e30f, l0 = 0.f, l1 = 0.f;
    float o_acc[8][4];
#pragma unroll
    for (int nt = 0; nt < 8; nt++)
#pragma unroll
        for (int r = 0; r < 4; r++) o_acc[nt][r] = 0.f;

    for (int kt = 0; kt < SEQ / 64; kt++) {
        int cur = kt & 1, nb = cur ^ 1;
        CP_WAIT0();
        __syncthreads();
        if (kt + 1 < SEQ / 64) {
            cp_tile(sbase + ((2 + 2 * nb) * TILE_W) * 4,
                    Kg + (size_t)(kt + 1) * 64 * HDIM, tid);
            cp_tile(sbase + ((3 + 2 * nb) * TILE_W) * 4,
                    Vg + (size_t)(kt + 1) * 64 * HDIM, tid);
            CP_COMMIT();
        }
        const uint32_t* Ks = smu + (2 + 2 * cur) * TILE_W;
        const uint32_t* Vs = smu + (3 + 2 * cur) * TILE_W;

        // ---- S = Q K^T ----
        float sacc[8][4];
#pragma unroll
        for (int nt = 0; nt < 8; nt++)
#pragma unroll
            for (int r = 0; r < 4; r++) sacc[nt][r] = 0.f;

#pragma unroll
        for (int ks = 0; ks < 8; ks++) {
            int kk = ks * 8 + c0;
            uint32_t a[4];
            a[0] = Qs[(warpM + r0) * ATS + kk];
            a[1] = Qs[(warpM + r0 + 8) * ATS + kk];
            a[2] = Qs[(warpM + r0) * ATS + kk + 4];
            a[3] = Qs[(warpM + r0 + 8) * ATS + kk + 4];
#pragma unroll
            for (int nt = 0; nt < 8; nt++) {
                uint32_t bb[2];
                bb[0] = Ks[(nt * 8 + r0) * ATS + kk];
                bb[1] = Ks[(nt * 8 + r0) * ATS + kk + 4];
                mma_tf32(sacc[nt], a, bb, sacc[nt]);
            }
        }

        // ---- online softmax ----
        float mt0 = -1e30f, mt1 = -1e30f;
#pragma unroll
        for (int nt = 0; nt < 8; nt++) {
#pragma unroll
            for (int r = 0; r < 4; r++) sacc[nt][r] *= 0.125f;
            mt0 = fmaxf(mt0, fmaxf(sacc[nt][0], sacc[nt][1]));
            mt1 = fmaxf(mt1, fmaxf(sacc[nt][2], sacc[nt][3]));
        }
        mt0 = fmaxf(mt0, __shfl_xor_sync(0xffffffffu, mt0, 1));
        mt0 = fmaxf(mt0, __shfl_xor_sync(0xffffffffu, mt0, 2));
        mt1 = fmaxf(mt1, __shfl_xor_sync(0xffffffffu, mt1, 1));
        mt1 = fmaxf(mt1, __shfl_xor_sync(0xffffffffu, mt1, 2));

        float mn0 = fmaxf(m0, mt0), mn1 = fmaxf(m1, mt1);
        float corr0 = __expf(m0 - mn0), corr1 = __expf(m1 - mn1);
        m0 = mn0; m1 = mn1;

        float rs0 = 0.f, rs1 = 0.f;
#pragma unroll
        for (int nt = 0; nt < 8; nt++) {
            float p00 = __expf(sacc[nt][0] - mn0);
            float p01 = __expf(sacc[nt][1] - mn0);
            float p10 = __expf(sacc[nt][2] - mn1);
            float p11 = __expf(sacc[nt][3] - mn1);
            rs0 += p00 + p01; rs1 += p10 + p11;
            uint2 u0 = make_uint2(f2tf32(p00), f2tf32(p01));
            uint2 u1 = make_uint2(f2tf32(p10), f2tf32(p11));
            *(uint2*)&Ps[(warpM + r0) * ATS + nt * 8 + 2 * c0] = u0;
            *(uint2*)&Ps[(warpM + r0 + 8) * ATS + nt * 8 + 2 * c0] = u1;
        }
        rs0 += __shfl_xor_sync(0xffffffffu, rs0, 1);
        rs0 += __shfl_xor_sync(0xffffffffu, rs0, 2);
        rs1 += __shfl_xor_sync(0xffffffffu, rs1, 1);
        rs1 += __shfl_xor_sync(0xffffffffu, rs1, 2);
        l0 = l0 * corr0 + rs0;
        l1 = l1 * corr1 + rs1;

#pragma unroll
        for (int nt = 0; nt < 8; nt++) {
            o_acc[nt][0] *= corr0; o_acc[nt][1] *= corr0;
            o_acc[nt][2] *= corr1; o_acc[nt][3] *= corr1;
        }
        __syncwarp();

        // ---- O += P @ V ----
#pragma unroll
        for (int ks = 0; ks < 8; ks++) {
            int kk = ks * 8;
            uint32_t a[4];
            a[0] = Ps[(warpM + r0) * ATS + kk + c0];
            a[1] = Ps[(warpM + r0 + 8) * ATS + kk + c0];
            a[2] = Ps[(warpM + r0) * ATS + kk + c0 + 4];
            a[3] = Ps[(warpM + r0 + 8) * ATS + kk + c0 + 4];
#pragma unroll
            for (int nt = 0; nt < 8; nt++) {
                uint32_t bb[2];
                bb[0] = Vs[(kk + c0) * ATS + nt * 8 + r0];
                bb[1] = Vs[(kk + c0 + 4) * ATS + nt * 8 + r0];
                mma_tf32(o_acc[nt], a, bb, o_acc[nt]);
            }
        }
    }

    // epilogue: /l, round, scatter to [B, L, H*64 + d]
    float inv0 = 1.0f / l0, inv1 = 1.0f / l1;
    size_t row0 = (size_t)b * SEQ + qt * 64 + warpM + r0;
    float* O0 = out + row0 * DMODEL + h * HDIM;
    float* O1 = O0 + 8 * DMODEL;
#pragma unroll
    for (int nt = 0; nt < 8; nt++) {
        int col = nt * 8 + 2 * c0;
        float2 a = make_float2(rnd_tf32(o_acc[nt][0] * inv0),
                               rnd_tf32(o_acc[nt][1] * inv0));
        float2 c = make_float2(rnd_tf32(o_acc[nt][2] * inv1),
                               rnd_tf32(o_acc[nt][3] * inv1));
        *(float2*)(O0 + col) = a;
        *(float2*)(O1 + col) = c;
    }
}

// =====================================================================
// LayerNorm over last dim (512). Block per row, 128 threads.
// Dual write: out_f = fp32 (residual stream), out_r = tf32-rounded
// (gemm A input). out_r may be null (final layer).
// =====================================================================
__global__ void __launch_bounds__(128) ln_kernel(
    const float* __restrict__ in, const float* __restrict__ g,
    const float* __restrict__ b, float* __restrict__ out_f,
    float* __restrict__ out_r)
{
    int row = blockIdx.x;
    int tid = threadIdx.x;
    float4 v4 = *(const float4*)(in + (size_t)row * DMODEL + tid * 4);
    float s  = v4.x + v4.y + v4.z + v4.w;
    float sq = v4.x * v4.x + v4.y * v4.y + v4.z * v4.z + v4.w * v4.w;
#pragma unroll
    for (int off = 16; off > 0; off >>= 1) {
        s  += __shfl_xor_sync(0xffffffffu, s, off);
        sq += __shfl_xor_sync(0xffffffffu, sq, off);
    }
    __shared__ float ss[4], sqs[4];
    int wid = tid >> 5;
    if ((tid & 31) == 0) { ss[wid] = s; sqs[wid] = sq; }
    __syncthreads();
    s  = ss[0] + ss[1] + ss[2] + ss[3];
    sq = sqs[0] + sqs[1] + sqs[2] + sqs[3];
    float mu  = s * (1.0f / DMODEL);
    float var = sq * (1.0f / DMODEL) - mu * mu;
    float inv = rsqrtf(var + 1e-5f);
    float4 gv = *(const float4*)(g + tid * 4);
    float4 bv = *(const float4*)(b + tid * 4);
    float4 o;
    o.x = (v4.x - mu) * inv * gv.x + bv.x;
    o.y = (v4.y - mu) * inv * gv.y + bv.y;
    o.z = (v4.z - mu) * inv * gv.z + bv.z;
    o.w = (v4.w - mu) * inv * gv.w + bv.w;
    *(float4*)(out_f + (size_t)row * DMODEL + tid * 4) = o;
    if (out_r)
        *(uint4*)(out_r + (size_t)row * DMODEL + tid * 4) = cvt4(o);
}

// =====================================================================
// host launcher
// =====================================================================
extern "C" void kernel_launch(void* const* d_in, const int* in_sizes, int n_in,
                              void* d_out, int out_size)
{
    const int*   src  = (const int*)  d_in[0];
    const float* emb  = (const float*)d_in[1];
    const float* pe   = (const float*)d_in[2];
    const float* Wq   = (const float*)d_in[3];
    const float* bq   = (const float*)d_in[4];
    const float* Wk   = (const float*)d_in[5];
    const float* bk   = (const float*)d_in[6];
    const float* Wv   = (const float*)d_in[7];
    const float* bv   = (const float*)d_in[8];
    const float* Wo   = (const float*)d_in[9];
    const float* bo   = (const float*)d_in[10];
    const float* W1   = (const float*)d_in[11];
    const float* b1   = (const float*)d_in[12];
    const float* W2   = (const float*)d_in[13];
    const float* b2   = (const float*)d_in[14];
    const float* g1   = (const float*)d_in[15];
    const float* be1  = (const float*)d_in[16];
    const float* g2   = (const float*)d_in[17];
    const float* be2  = (const float*)d_in[18];
    float* outp = (float*)d_out;

    float *x, *xr, *q, *k, *v, *attn, *tmp, *ff, *wr;
    cudaGetSymbolAddress((void**)&x,    g_x);
    cudaGetSymbolAddress((void**)&xr,   g_xr);
    cudaGetSymbolAddress((void**)&q,    g_q);
    cudaGetSymbolAddress((void**)&k,    g_k);
    cudaGetSymbolAddress((void**)&v,    g_v);
    cudaGetSymbolAddress((void**)&attn, g_attn);
    cudaGetSymbolAddress((void**)&tmp,  g_tmp);
    cudaGetSymbolAddress((void**)&ff,   g_ff);
    cudaGetSymbolAddress((void**)&wr,   g_wr);

    cudaFuncSetAttribute(attn_mma,
                         cudaFuncAttributeMaxDynamicSharedMemorySize, ATTN3_SMEM);
    cudaFuncSetAttribute(gemm_mma,
                         cudaFuncAttributeMaxDynamicSharedMemorySize, GS3_SMEM);
    cudaFuncSetAttribute(gemm_qkv,
                         cudaFuncAttributeMaxDynamicSharedMemorySize, GS3_SMEM);

    const size_t DD6 = (size_t)NLAYERS * DMODEL * DMODEL;
    const size_t DF6 = (size_t)NLAYERS * DMODEL * DFF;
    float* WqR = wr;
    float* WkR = WqR + DD6;
    float* WvR = WkR + DD6;
    float* WoR = WvR + DD6;
    float* W1R = WoR + DD6;
    float* W2R = W1R + DF6;

    round4_kernel<<<dim3((unsigned)(DD6 / 4 / 256), 1, 4), 256>>>(
        Wq, Wk, Wv, Wo, WqR, WkR, WvR, WoR);
    round2_kernel<<<dim3((unsigned)(DF6 / 4 / 256), 1, 2), 256>>>(
        W1, W2, W1R, W2R);

    embed_kernel<<<MROWS, 128>>>(src, emb, pe, x, xr);

    dim3 gQKV(DMODEL / 128, MROWS / 128, 3);
    dim3 gProj(DMODEL / 128, MROWS / 128);
    dim3 gFF1(DFF / 128,    MROWS / 128);
    dim3 gAttn(SEQ / 64, BATCH * NHEADS);

    for (int L = 0; L < NLAYERS; L++) {
        const size_t wdd = (size_t)L * DMODEL * DMODEL;
        const size_t wdf = (size_t)L * DMODEL * DFF;
        const size_t vd  = (size_t)L * DMODEL;
        const size_t vf  = (size_t)L * DFF;

        gemm_qkv<<<gQKV, 256, GS3_SMEM>>>(xr, WqR + wdd, WkR + wdd, WvR + wdd,
                                          bq + vd, bk + vd, bv + vd, q, k, v);

        attn_mma<<<gAttn, 128, ATTN3_SMEM>>>(q, k, v, attn);

        gemm_mma<<<gProj, 256, GS3_SMEM>>>(attn, WoR + wdd, bo + vd, x, tmp,
                                           MROWS, DMODEL, DMODEL, 0, 0);
        ln_kernel<<<MROWS, 128>>>(tmp, g1 + vd, be1 + vd, x, xr);

        gemm_mma<<<gFF1, 256, GS3_SMEM>>>(xr, W1R + wdf, b1 + vf, nullptr, ff,
                                          MROWS, DFF, DMODEL, 1, 1);
        gemm_mma<<<gProj, 256, GS3_SMEM>>>(ff, W2R + wdf, b2 + vd, x, tmp,
                                           MROWS, DMODEL, DFF, 0, 0);
        ln_kernel<<<MROWS, 128>>>(tmp, g2 + vd, be2 + vd,
                                  (L == NLAYERS - 1) ? outp : x,
                                  (L == NLAYERS - 1) ? nullptr : xr);
    }
}